// round 2
// baseline (speedup 1.0000x reference)
#include <cuda_runtime.h>

// EfConv: out[n, k*64+o] = sum_{e: dst_e=n} ef[e,k] * (node_feat[src_e] . W[o]) + b[o]
// y = X @ W^T first (8x smaller GEMM). CSR-by-dst built per launch, but the CSR
// payload is only (src, edge_id) int2 per edge -- ef rows are gathered in the
// main pass (ef + y both L2-resident: 38 MB < 126 MB L2).

#define MAXN 50000
#define MAXE 800000
#define NF 64
#define ED 8

// Scratch (static __device__ arrays; no allocation anywhere)
__device__ int   g_deg[MAXN];
__device__ int   g_off[MAXN + 1];
__device__ int   g_cur[MAXN];
__device__ int2  g_edge[MAXE];               // (src, edge_id), dst-grouped
__device__ float g_y[(size_t)MAXN * NF];     // 12.8 MB, L2-resident

// ---------------- CSR build ----------------

__global__ void k_zero_deg(int N) {
    int i = blockIdx.x * blockDim.x + threadIdx.x;
    if (i < N) g_deg[i] = 0;
}

// 4 edges per thread via int4 reads of dst.
__global__ void k_hist(const int* __restrict__ dst, int E) {
    int t = blockIdx.x * blockDim.x + threadIdx.x;
    int e = t * 4;
    if (e + 4 <= E) {
        int4 d = *(const int4*)(dst + e);
        atomicAdd(&g_deg[d.x], 1);
        atomicAdd(&g_deg[d.y], 1);
        atomicAdd(&g_deg[d.z], 1);
        atomicAdd(&g_deg[d.w], 1);
    } else {
        for (; e < E; e++) atomicAdd(&g_deg[dst[e]], 1);
    }
}

// Single-block exclusive scan of g_deg -> g_off (and cursor copy).
__global__ void k_scan(int N) {
    __shared__ int sh[1024];
    int t = threadIdx.x;
    int chunk = (N + 1023) / 1024;
    int beg = t * chunk;
    int end = min(beg + chunk, N);
    int s = 0;
    for (int i = beg; i < end; i++) s += g_deg[i];
    sh[t] = s;
    __syncthreads();
    for (int d = 1; d < 1024; d <<= 1) {
        int v = (t >= d) ? sh[t - d] : 0;
        __syncthreads();
        sh[t] += v;
        __syncthreads();
    }
    int run = (t == 0) ? 0 : sh[t - 1];
    for (int i = beg; i < end; i++) {
        g_off[i] = run;
        g_cur[i] = run;
        run += g_deg[i];
    }
    if (t == 1023) g_off[N] = run;   // == E
}

// Scatter only (src, edge_id): 8B per edge instead of 36B.
__global__ void k_scatter(const int* __restrict__ src, const int* __restrict__ dst, int E) {
    int e = blockIdx.x * blockDim.x + threadIdx.x;
    if (e >= E) return;
    int pos = atomicAdd(&g_cur[dst[e]], 1);
    g_edge[pos] = make_int2(src[e], e);
}

// ---------------- y = X @ W^T ----------------
__global__ void k_ygemm(const float* __restrict__ X, const float* __restrict__ W, int N) {
    __shared__ float Ws[64][68];
    __shared__ float xs[16][64];
    int t = threadIdx.x;
    int base = blockIdx.x * 16;

    for (int idx = t; idx < 64 * 64; idx += 256)
        Ws[idx >> 6][idx & 63] = W[idx];
    for (int idx = t; idx < 16 * 64; idx += 256) {
        int ln = idx >> 6, i = idx & 63;
        int n = base + ln;
        xs[ln][i] = (n < N) ? X[(size_t)n * NF + i] : 0.f;
    }
    __syncthreads();

    int o = t & 63;
    int g = t >> 6;
    float acc[4] = {0.f, 0.f, 0.f, 0.f};
    #pragma unroll
    for (int i = 0; i < 64; i += 4) {
        float4 wv = *(const float4*)&Ws[o][i];
        #pragma unroll
        for (int r = 0; r < 4; r++) {
            float4 xv = *(const float4*)&xs[g * 4 + r][i];
            acc[r] += wv.x * xv.x + wv.y * xv.y + wv.z * xv.z + wv.w * xv.w;
        }
    }
    #pragma unroll
    for (int r = 0; r < 4; r++) {
        int n = base + g * 4 + r;
        if (n < N) g_y[(size_t)n * NF + o] = acc[r];
    }
}

// ---------------- main: warp-per-node segmented reduction ----------------
// 4-edge batches for MLP on the dependent (src -> y) and (eid -> ef) gathers.
__device__ __forceinline__ void fma_edge(float (&acc)[16], float4 ea, float4 eb, float2 yv) {
    acc[0]  += ea.x * yv.x;  acc[1]  += ea.x * yv.y;
    acc[2]  += ea.y * yv.x;  acc[3]  += ea.y * yv.y;
    acc[4]  += ea.z * yv.x;  acc[5]  += ea.z * yv.y;
    acc[6]  += ea.w * yv.x;  acc[7]  += ea.w * yv.y;
    acc[8]  += eb.x * yv.x;  acc[9]  += eb.x * yv.y;
    acc[10] += eb.y * yv.x;  acc[11] += eb.y * yv.y;
    acc[12] += eb.z * yv.x;  acc[13] += eb.z * yv.y;
    acc[14] += eb.w * yv.x;  acc[15] += eb.w * yv.y;
}

__global__ void __launch_bounds__(256) k_main(const float* __restrict__ ef,
                                              const float* __restrict__ bvec,
                                              float* __restrict__ out, int N) {
    int w = (blockIdx.x * blockDim.x + threadIdx.x) >> 5;
    if (w >= N) return;
    int lane = threadIdx.x & 31;
    int beg = g_off[w], end = g_off[w + 1];

    float acc[16];
    #pragma unroll
    for (int a = 0; a < 16; a++) acc[a] = 0.f;

    int j = beg;
    for (; j + 4 <= end; j += 4) {
        int2 d0 = g_edge[j];
        int2 d1 = g_edge[j + 1];
        int2 d2 = g_edge[j + 2];
        int2 d3 = g_edge[j + 3];
        const float4* p0 = (const float4*)(ef + (size_t)d0.y * ED);
        const float4* p1 = (const float4*)(ef + (size_t)d1.y * ED);
        const float4* p2 = (const float4*)(ef + (size_t)d2.y * ED);
        const float4* p3 = (const float4*)(ef + (size_t)d3.y * ED);
        float4 ea0 = p0[0], eb0 = p0[1];
        float4 ea1 = p1[0], eb1 = p1[1];
        float4 ea2 = p2[0], eb2 = p2[1];
        float4 ea3 = p3[0], eb3 = p3[1];
        float2 y0 = *(const float2*)(g_y + (size_t)d0.x * NF + lane * 2);
        float2 y1 = *(const float2*)(g_y + (size_t)d1.x * NF + lane * 2);
        float2 y2 = *(const float2*)(g_y + (size_t)d2.x * NF + lane * 2);
        float2 y3 = *(const float2*)(g_y + (size_t)d3.x * NF + lane * 2);
        fma_edge(acc, ea0, eb0, y0);
        fma_edge(acc, ea1, eb1, y1);
        fma_edge(acc, ea2, eb2, y2);
        fma_edge(acc, ea3, eb3, y3);
    }
    for (; j < end; j++) {
        int2 d = g_edge[j];
        const float4* p = (const float4*)(ef + (size_t)d.y * ED);
        float4 ea = p[0], eb = p[1];
        float2 yv = *(const float2*)(g_y + (size_t)d.x * NF + lane * 2);
        fma_edge(acc, ea, eb, yv);
    }

    float2 bb = *(const float2*)(bvec + lane * 2);
    float* op = out + (size_t)w * (ED * NF);
    #pragma unroll
    for (int k = 0; k < ED; k++) {
        float2 v;
        v.x = acc[2 * k]     + bb.x;
        v.y = acc[2 * k + 1] + bb.y;
        *(float2*)(op + k * NF + lane * 2) = v;
    }
}

// ---------------- launch ----------------

extern "C" void kernel_launch(void* const* d_in, const int* in_sizes, int n_in,
                              void* d_out, int out_size) {
    const float* node_feat = (const float*)d_in[0];
    const float* edge_feat = (const float*)d_in[1];
    const float* W         = (const float*)d_in[2];
    const float* b         = (const float*)d_in[3];
    const int*   src       = (const int*)d_in[4];
    const int*   dst       = (const int*)d_in[5];

    int N = in_sizes[0] / NF;     // 50000
    int E = in_sizes[4];          // 800000

    k_zero_deg<<<(N + 255) / 256, 256>>>(N);
    k_hist   <<<(E / 4 + 255) / 256, 256>>>(dst, E);
    k_scan   <<<1, 1024>>>(N);
    k_scatter<<<(E + 255) / 256, 256>>>(src, dst, E);
    k_ygemm  <<<(N + 15) / 16, 256>>>(node_feat, W, N);
    k_main   <<<(N * 32 + 255) / 256, 256>>>(edge_feat, b, (float*)d_out, N);
}